// round 1
// baseline (speedup 1.0000x reference)
#include <cuda_runtime.h>
#include <cstdint>

// ============================================================================
// ExampleModel_67705864454161: fused int8 fake-quant conv3x3 (5->10) + conv3x3
// (10->10) with per-tensor power-of-two scales. Exact integer arithmetic:
//   x_q = clamp(rint(x/s_in))           int8
//   acc1 = sum w1_q * x_q               int32 (exact, |acc| < 2^20)
//   y_q  = clamp(rint((acc1+b1_i)*m1))  int8, m1 = s_in*s_w1/s_o1
//   acc2 = sum w2_q * y_q               int32 (exact, |acc| < 2^21)
//   out  = clamp(rint((acc2+b2_i)*m2)) * s_o2
// All rounding is round-half-even (__float2int_rn == jnp.round), all scales
// are powers of two, so this is bit-exact vs the reference.
// ============================================================================

#define TH 32
#define TW 32

// Derived constants & packed weights (filled by prep_kernel; no allocations).
__device__ float g_consts[4];     // inv_s_in, m1, m2, s_o2
__device__ int   g_b1i[10];
__device__ int   g_b2i[10];
__device__ uint2 g_w1p[90];       // [oc][tap] : 5 int8 ch (3 zero-pad) in 2 words
__device__ uint4 g_w2p[90];       // [oc][tap] : 10 int8 ch (6 zero-pad) in 4 words

__device__ __forceinline__ int clampq(float v) {
    int q = __float2int_rn(v);
    return max(-128, min(127, q));
}

__global__ void prep_kernel(const float* __restrict__ w1, const float* __restrict__ b1,
                            const float* __restrict__ w2, const float* __restrict__ b2,
                            const float* __restrict__ s_in, const float* __restrict__ s_w1,
                            const float* __restrict__ s_o1, const float* __restrict__ s_w2,
                            const float* __restrict__ s_o2) {
    const int t = threadIdx.x;
    const float si = s_in[0], sw1 = s_w1[0], so1 = s_o1[0], sw2 = s_w2[0], so2 = s_o2[0];
    if (t == 0) {
        g_consts[0] = 1.0f / si;            // exact (pow2)
        g_consts[1] = (si * sw1) / so1;     // exact (pow2)
        g_consts[2] = (so1 * sw2) / so2;    // exact (pow2)
        g_consts[3] = so2;
    }
    if (t < 10) {
        g_b1i[t] = clampq(b1[t] / (si * sw1));
        g_b2i[t] = clampq(b2[t] / (so1 * sw2));
    }
    for (int idx = t; idx < 90; idx += blockDim.x) {
        const int oc = idx / 9, tap = idx % 9;
        const int ky = tap / 3, kx = tap % 3;
        // conv1 weights: [10][5][3][3]
        unsigned bq[5];
        #pragma unroll
        for (int c = 0; c < 5; c++) {
            int q = clampq(w1[((oc * 5 + c) * 3 + ky) * 3 + kx] / sw1);
            bq[c] = (unsigned)(q & 0xFF);
        }
        uint2 p1;
        p1.x = bq[0] | (bq[1] << 8) | (bq[2] << 16) | (bq[3] << 24);
        p1.y = bq[4];
        g_w1p[idx] = p1;
        // conv2 weights: [10][10][3][3]
        unsigned cq[10];
        #pragma unroll
        for (int c = 0; c < 10; c++) {
            int q = clampq(w2[((oc * 10 + c) * 3 + ky) * 3 + kx] / sw2);
            cq[c] = (unsigned)(q & 0xFF);
        }
        uint4 p2;
        p2.x = cq[0] | (cq[1] << 8) | (cq[2] << 16) | (cq[3] << 24);
        p2.y = cq[4] | (cq[5] << 8) | (cq[6] << 16) | (cq[7] << 24);
        p2.z = cq[8] | (cq[9] << 8);
        p2.w = 0u;
        g_w2p[idx] = p2;
    }
}

__global__ __launch_bounds__(256)
void fused_conv_kernel(const float* __restrict__ x, float* __restrict__ out) {
    __shared__ uint2 xs[36][36];     // quantized x tile, 8 ch packed (5 used)
    __shared__ uint4 ys[34][34];     // quantized y tile, 16 ch packed (10 used)
    __shared__ uint2 w1s[90];
    __shared__ uint4 w2s[90];
    __shared__ int   b1s[10], b2s[10];
    __shared__ float cs[4];

    const int tid = threadIdx.x;
    const int n  = blockIdx.z;
    const int ty = blockIdx.y * TH;
    const int tx = blockIdx.x * TW;

    if (tid < 90) { w1s[tid] = g_w1p[tid]; w2s[tid] = g_w2p[tid]; }
    if (tid < 10) { b1s[tid] = g_b1i[tid]; b2s[tid] = g_b2i[tid]; }
    if (tid < 4)  { cs[tid] = g_consts[tid]; }
    __syncthreads();
    const float inv_s_in = cs[0], m1 = cs[1], m2 = cs[2], so2 = cs[3];

    // ---- Phase A: load + quantize x tile (36x36, 5 channels) ----
    const float* xb = x + (size_t)n * 5u * 512u * 512u;
    for (int idx = tid; idx < 36 * 36; idx += 256) {
        const int r = idx / 36, c = idx % 36;
        const int gy = ty + r, gx = tx + c;
        uint2 p = make_uint2(0u, 0u);
        if (gy < 512 && gx < 512) {
            const float* px = xb + (size_t)gy * 512 + gx;
            const unsigned q0 = (unsigned)(clampq(px[0]       * inv_s_in) & 0xFF);
            const unsigned q1 = (unsigned)(clampq(px[262144]  * inv_s_in) & 0xFF);
            const unsigned q2 = (unsigned)(clampq(px[524288]  * inv_s_in) & 0xFF);
            const unsigned q3 = (unsigned)(clampq(px[786432]  * inv_s_in) & 0xFF);
            const unsigned q4 = (unsigned)(clampq(px[1048576] * inv_s_in) & 0xFF);
            p.x = q0 | (q1 << 8) | (q2 << 16) | (q3 << 24);
            p.y = q4;
        }
        xs[r][c] = p;
    }
    __syncthreads();

    // ---- Phase B: conv1 (5->10) + requant into ys ----
    for (int p = tid; p < 34 * 34; p += 256) {
        const int r = p / 34, c = p % 34;
        uint2 xv[9];
        #pragma unroll
        for (int t = 0; t < 9; t++) xv[t] = xs[r + t / 3][c + t % 3];
        unsigned ow0 = 0u, ow1 = 0u, ow2 = 0u;
        #pragma unroll
        for (int oc = 0; oc < 10; oc++) {
            int acc = 0;
            #pragma unroll
            for (int t = 0; t < 9; t++) {
                const uint2 wv = w1s[oc * 9 + t];
                acc = __dp4a((int)xv[t].x, (int)wv.x, acc);
                acc = __dp4a((int)xv[t].y, (int)wv.y, acc);
            }
            const int q = clampq((float)(acc + b1s[oc]) * m1);
            const unsigned b = (unsigned)(q & 0xFF);
            if (oc < 4)      ow0 |= b << (8 * oc);
            else if (oc < 8) ow1 |= b << (8 * (oc - 4));
            else             ow2 |= b << (8 * (oc - 8));
        }
        ys[r][c] = make_uint4(ow0, ow1, ow2, 0u);
    }
    __syncthreads();

    // ---- Phase C: conv2 (10->10) + requant + store ----
    float* ob = out + (size_t)n * 10u * 508u * 508u;
    for (int p = tid; p < 32 * 32; p += 256) {
        const int r = p / 32, c = p % 32;
        const int gy = ty + r, gx = tx + c;
        const bool valid = (gy < 508) && (gx < 508);
        uint4 yv[9];
        #pragma unroll
        for (int t = 0; t < 9; t++) yv[t] = ys[r + t / 3][c + t % 3];
        #pragma unroll
        for (int oc = 0; oc < 10; oc++) {
            int acc = 0;
            #pragma unroll
            for (int t = 0; t < 9; t++) {
                const uint4 wv = w2s[oc * 9 + t];
                acc = __dp4a((int)yv[t].x, (int)wv.x, acc);
                acc = __dp4a((int)yv[t].y, (int)wv.y, acc);
                acc = __dp4a((int)yv[t].z, (int)wv.z, acc);
            }
            const int q = clampq((float)(acc + b2s[oc]) * m2);
            if (valid) ob[(size_t)oc * 258064u + (size_t)gy * 508u + gx] = (float)q * so2;
        }
    }
}

extern "C" void kernel_launch(void* const* d_in, const int* in_sizes, int n_in,
                              void* d_out, int out_size) {
    const float* x    = (const float*)d_in[0];
    const float* w1   = (const float*)d_in[1];
    const float* b1   = (const float*)d_in[2];
    const float* w2   = (const float*)d_in[3];
    const float* b2   = (const float*)d_in[4];
    const float* s_in = (const float*)d_in[5];
    const float* s_w1 = (const float*)d_in[6];
    const float* s_o1 = (const float*)d_in[7];
    const float* s_w2 = (const float*)d_in[8];
    const float* s_o2 = (const float*)d_in[9];

    prep_kernel<<<1, 128>>>(w1, b1, w2, b2, s_in, s_w1, s_o1, s_w2, s_o2);

    dim3 grid(16, 16, 32);   // 16x16 tiles of 32x32 over 508x508, 32 batch
    fused_conv_kernel<<<grid, 256>>>(x, (float*)d_out);
}

// round 2
// speedup vs baseline: 1.4566x; 1.4566x over previous
#include <cuda_runtime.h>
#include <cstdint>

// ============================================================================
// Fused int8 fake-quant conv3x3(5->10) + conv3x3(10->10), pow2 scales.
// Bit-exact integer arithmetic (see R1). This round: 4-pixel strips,
// split channel packing (packed quads + byte planes), row-conv dp4a trick,
// STG.128 output stores. Targets the L1tex(shared) bottleneck seen in ncu.
// ============================================================================

__device__ float g_consts[4];       // inv_s_in, m1, m2, s_o2
__device__ int   g_b1i[10];
__device__ int   g_b2i[10];
__device__ unsigned g_w1a[90];      // [oc*9+tap]: ch0-3 packed
__device__ unsigned g_w1b[30];      // [oc*3+ky]:  [w4_kx0,w4_kx1,w4_kx2,0]
__device__ uint2    g_w2a[90];      // [oc*9+tap]: ch0-7 packed
__device__ uint2    g_w2b[30];      // [oc*3+ky]:  .x=ch8 row word, .y=ch9

__device__ __forceinline__ int clampq(float v) {
    int q = __float2int_rn(v);
    return max(-128, min(127, q));
}

__global__ void prep_kernel(const float* __restrict__ w1, const float* __restrict__ b1,
                            const float* __restrict__ w2, const float* __restrict__ b2,
                            const float* __restrict__ s_in, const float* __restrict__ s_w1,
                            const float* __restrict__ s_o1, const float* __restrict__ s_w2,
                            const float* __restrict__ s_o2) {
    const int t = threadIdx.x;
    const float si = s_in[0], sw1 = s_w1[0], so1 = s_o1[0], sw2 = s_w2[0], so2 = s_o2[0];
    if (t == 0) {
        g_consts[0] = 1.0f / si;
        g_consts[1] = (si * sw1) / so1;
        g_consts[2] = (so1 * sw2) / so2;
        g_consts[3] = so2;
    }
    if (t < 10) {
        g_b1i[t] = clampq(b1[t] / (si * sw1));
        g_b2i[t] = clampq(b2[t] / (so1 * sw2));
    }
    if (t < 90) {
        const int oc = t / 9, tap = t % 9;
        const int ky = tap / 3, kx = tap % 3;
        // conv1 packed ch0-3
        unsigned a = 0;
        #pragma unroll
        for (int c = 0; c < 4; c++) {
            int q = clampq(w1[((oc * 5 + c) * 3 + ky) * 3 + kx] / sw1);
            a |= ((unsigned)(q & 0xFF)) << (8 * c);
        }
        g_w1a[t] = a;
        // conv2 packed ch0-7
        uint2 p; p.x = 0u; p.y = 0u;
        #pragma unroll
        for (int c = 0; c < 8; c++) {
            int q = clampq(w2[((oc * 10 + c) * 3 + ky) * 3 + kx] / sw2);
            unsigned b = (unsigned)(q & 0xFF);
            if (c < 4) p.x |= b << (8 * c); else p.y |= b << (8 * (c - 4));
        }
        g_w2a[t] = p;
    }
    if (t < 30) {
        const int oc = t / 3, ky = t % 3;
        // conv1 ch4 row word
        unsigned b = 0;
        #pragma unroll
        for (int kx = 0; kx < 3; kx++) {
            int q = clampq(w1[((oc * 5 + 4) * 3 + ky) * 3 + kx] / sw1);
            b |= ((unsigned)(q & 0xFF)) << (8 * kx);
        }
        g_w1b[t] = b;
        // conv2 ch8/ch9 row words
        uint2 p; p.x = 0u; p.y = 0u;
        #pragma unroll
        for (int kx = 0; kx < 3; kx++) {
            int q8 = clampq(w2[((oc * 10 + 8) * 3 + ky) * 3 + kx] / sw2);
            int q9 = clampq(w2[((oc * 10 + 9) * 3 + ky) * 3 + kx] / sw2);
            p.x |= ((unsigned)(q8 & 0xFF)) << (8 * kx);
            p.y |= ((unsigned)(q9 & 0xFF)) << (8 * kx);
        }
        g_w2b[t] = p;
    }
}

__global__ __launch_bounds__(256)
void fused_conv_kernel(const float* __restrict__ x, float* __restrict__ out) {
    __shared__ unsigned xs4[36][36];   // x quantized: ch0-3 packed per pixel
    __shared__ unsigned xs1w[36][10];  // x ch4 byte plane (word = 4 cols)
    __shared__ uint2    ys2[34][36];   // y quantized: ch0-7 packed per pixel
    __shared__ unsigned ys8w[34][10];  // y ch8 byte plane
    __shared__ unsigned ys9w[34][10];  // y ch9 byte plane
    __shared__ unsigned w1a[90], w1b[30];
    __shared__ uint2    w2a[90], w2b[30];
    __shared__ int b1s[10], b2s[10];
    __shared__ float cs[4];

    const int tid = threadIdx.x;
    const int n  = blockIdx.z;
    const int ty = blockIdx.y * 32;
    const int tx = blockIdx.x * 32;

    if (tid < 90) { w1a[tid] = g_w1a[tid]; w2a[tid] = g_w2a[tid]; }
    if (tid < 30) { w1b[tid] = g_w1b[tid]; w2b[tid] = g_w2b[tid]; }
    if (tid < 10) { b1s[tid] = g_b1i[tid]; b2s[tid] = g_b2i[tid]; }
    if (tid < 4)  { cs[tid] = g_consts[tid]; }
    if (tid < 36) { xs1w[tid][9] = 0u; }   // pad word (read by windows, x0 weight)
    __syncthreads();
    const float inv_s_in = cs[0], m1 = cs[1], m2 = cs[2], so2 = cs[3];

    // ---- Phase A: load + quantize x tile (36x36, 5 ch) ----
    const float* xb = x + (size_t)n * 5u * 512u * 512u;
    for (int idx = tid; idx < 36 * 36; idx += 256) {
        const int r = idx / 36, c = idx % 36;
        const int gy = ty + r, gx = tx + c;
        unsigned p = 0u, q4 = 0u;
        if (gy < 512 && gx < 512) {
            const float* px = xb + (size_t)gy * 512 + gx;
            const unsigned q0 = (unsigned)(clampq(px[0]       * inv_s_in) & 0xFF);
            const unsigned q1 = (unsigned)(clampq(px[262144]  * inv_s_in) & 0xFF);
            const unsigned q2 = (unsigned)(clampq(px[524288]  * inv_s_in) & 0xFF);
            const unsigned q3 = (unsigned)(clampq(px[786432]  * inv_s_in) & 0xFF);
            q4 = (unsigned)(clampq(px[1048576] * inv_s_in) & 0xFF);
            p = q0 | (q1 << 8) | (q2 << 16) | (q3 << 24);
        }
        xs4[r][c] = p;
        ((unsigned char*)&xs1w[r][0])[c] = (unsigned char)q4;
    }
    __syncthreads();

    // ---- Phase B: conv1 (5->10), 4-pixel strips, requant into ys ----
    for (int s = tid; s < 34 * 9; s += 256) {
        const int r = s / 9, wi = s % 9, cb = wi * 4;
        int xv[3][6];
        #pragma unroll
        for (int ky = 0; ky < 3; ky++)
            #pragma unroll
            for (int j = 0; j < 6; j++) {
                int col = cb + j; col = (col > 35) ? 35 : col;
                xv[ky][j] = (int)xs4[r + ky][col];
            }
        int win[3][4];
        #pragma unroll
        for (int ky = 0; ky < 3; ky++) {
            const unsigned A = xs1w[r + ky][wi];
            const unsigned B = xs1w[r + ky][wi + 1];
            win[ky][0] = (int)A;
            win[ky][1] = (int)__byte_perm(A, B, 0x4321);
            win[ky][2] = (int)__byte_perm(A, B, 0x5432);
            win[ky][3] = (int)__byte_perm(A, B, 0x6543);
        }
        unsigned o0[4] = {0u,0u,0u,0u}, o1[4] = {0u,0u,0u,0u}, o8 = 0u, o9 = 0u;
        #pragma unroll
        for (int oc = 0; oc < 10; oc++) {
            int acc[4];
            #pragma unroll
            for (int i = 0; i < 4; i++) acc[i] = b1s[oc];
            #pragma unroll
            for (int ky = 0; ky < 3; ky++) {
                #pragma unroll
                for (int kx = 0; kx < 3; kx++) {
                    const int w = (int)w1a[oc * 9 + ky * 3 + kx];
                    #pragma unroll
                    for (int i = 0; i < 4; i++)
                        acc[i] = __dp4a(xv[ky][i + kx], w, acc[i]);
                }
                const int wb = (int)w1b[oc * 3 + ky];
                #pragma unroll
                for (int i = 0; i < 4; i++)
                    acc[i] = __dp4a(win[ky][i], wb, acc[i]);
            }
            #pragma unroll
            for (int i = 0; i < 4; i++) {
                const unsigned q = (unsigned)(clampq((float)acc[i] * m1) & 0xFF);
                if (oc < 4)       o0[i] |= q << (8 * oc);
                else if (oc < 8)  o1[i] |= q << (8 * (oc - 4));
                else if (oc == 8) o8 |= q << (8 * i);
                else              o9 |= q << (8 * i);
            }
        }
        #pragma unroll
        for (int i = 0; i < 4; i++) ys2[r][cb + i] = make_uint2(o0[i], o1[i]);
        ys8w[r][wi] = o8;
        ys9w[r][wi] = o9;
    }
    __syncthreads();

    // ---- Phase C: conv2 (10->10), 4-pixel strips, requant + STG.128 ----
    {
        const int r  = tid >> 3;          // 0..31
        const int wi = tid & 7;           // 0..7
        const int cb = wi * 4;
        int yvx[3][6], yvy[3][6];
        #pragma unroll
        for (int ky = 0; ky < 3; ky++)
            #pragma unroll
            for (int j = 0; j < 6; j++) {
                const uint2 v = ys2[r + ky][cb + j];
                yvx[ky][j] = (int)v.x; yvy[ky][j] = (int)v.y;
            }
        int w8[3][4], w9[3][4];
        #pragma unroll
        for (int ky = 0; ky < 3; ky++) {
            const unsigned A8 = ys8w[r + ky][wi], B8 = ys8w[r + ky][wi + 1];
            const unsigned A9 = ys9w[r + ky][wi], B9 = ys9w[r + ky][wi + 1];
            w8[ky][0] = (int)A8;
            w8[ky][1] = (int)__byte_perm(A8, B8, 0x4321);
            w8[ky][2] = (int)__byte_perm(A8, B8, 0x5432);
            w8[ky][3] = (int)__byte_perm(A8, B8, 0x6543);
            w9[ky][0] = (int)A9;
            w9[ky][1] = (int)__byte_perm(A9, B9, 0x4321);
            w9[ky][2] = (int)__byte_perm(A9, B9, 0x5432);
            w9[ky][3] = (int)__byte_perm(A9, B9, 0x6543);
        }
        const int gy = ty + r, gx = tx + cb;
        const bool valid = (gy < 508) && (gx < 508);
        float* ob = out + (size_t)n * 2580640u + (size_t)gy * 508u + gx;
        #pragma unroll
        for (int oc = 0; oc < 10; oc++) {
            int acc[4];
            #pragma unroll
            for (int i = 0; i < 4; i++) acc[i] = b2s[oc];
            #pragma unroll
            for (int ky = 0; ky < 3; ky++) {
                #pragma unroll
                for (int kx = 0; kx < 3; kx++) {
                    const uint2 w = w2a[oc * 9 + ky * 3 + kx];
                    #pragma unroll
                    for (int i = 0; i < 4; i++) {
                        acc[i] = __dp4a(yvx[ky][i + kx], (int)w.x, acc[i]);
                        acc[i] = __dp4a(yvy[ky][i + kx], (int)w.y, acc[i]);
                    }
                }
                const uint2 wb = w2b[oc * 3 + ky];
                #pragma unroll
                for (int i = 0; i < 4; i++) {
                    acc[i] = __dp4a(w8[ky][i], (int)wb.x, acc[i]);
                    acc[i] = __dp4a(w9[ky][i], (int)wb.y, acc[i]);
                }
            }
            if (valid) {
                float4 v;
                v.x = (float)clampq((float)acc[0] * m2) * so2;
                v.y = (float)clampq((float)acc[1] * m2) * so2;
                v.z = (float)clampq((float)acc[2] * m2) * so2;
                v.w = (float)clampq((float)acc[3] * m2) * so2;
                *(float4*)(ob + (size_t)oc * 258064u) = v;
            }
        }
    }
}

extern "C" void kernel_launch(void* const* d_in, const int* in_sizes, int n_in,
                              void* d_out, int out_size) {
    const float* x    = (const float*)d_in[0];
    const float* w1   = (const float*)d_in[1];
    const float* b1   = (const float*)d_in[2];
    const float* w2   = (const float*)d_in[3];
    const float* b2   = (const float*)d_in[4];
    const float* s_in = (const float*)d_in[5];
    const float* s_w1 = (const float*)d_in[6];
    const float* s_o1 = (const float*)d_in[7];
    const float* s_w2 = (const float*)d_in[8];
    const float* s_o2 = (const float*)d_in[9];

    prep_kernel<<<1, 128>>>(w1, b1, w2, b2, s_in, s_w1, s_o1, s_w2, s_o2);

    dim3 grid(16, 16, 32);   // 16x16 tiles of 32x32 over 508x508, batch 32
    fused_conv_kernel<<<grid, 256>>>(x, (float*)d_out);
}

// round 3
// speedup vs baseline: 1.7764x; 1.2196x over previous
#include <cuda_runtime.h>
#include <cstdint>

// ============================================================================
// Fused int8 fake-quant conv3x3(5->10) + conv3x3(10->10), pow2 scales.
// Bit-exact integer arithmetic. R3: 128-thr blocks / 32x16 tiles (balanced
// phases, 5 blocks/SM), 6-px conv1 strips, cvt.rni.sat.s8 quantization,
// PRMT packing, LDS.128 data loads, STG.128 stores.
// ============================================================================

__device__ float g_consts[4];       // inv_s_in, m1, m2, s_o2
__device__ int   g_b1i[10];
__device__ int   g_b2i[10];
__device__ unsigned g_w1a[90];      // [oc*9+tap]: ch0-3 packed
__device__ unsigned g_w1b[30];      // [oc*3+ky]:  [w4_kx0,w4_kx1,w4_kx2,0]
__device__ uint2    g_w2a[90];      // [oc*9+tap]: ch0-7 packed
__device__ uint2    g_w2b[30];      // [oc*3+ky]:  .x=ch8 row word, .y=ch9

__device__ __forceinline__ int clampq(float v) {
    int q = __float2int_rn(v);
    return max(-128, min(127, q));
}
// round-half-even + saturate to s8. Only the LOW BYTE is guaranteed usable.
__device__ __forceinline__ unsigned q8b(float v) {
    unsigned r;
    asm("cvt.rni.sat.s8.f32 %0, %1;" : "=r"(r) : "f"(v));
    return r;
}
// full-integer result (sign guaranteed): float clamp then round
__device__ __forceinline__ int qclampf(float v) {
    return __float2int_rn(fminf(fmaxf(v, -128.0f), 127.0f));
}

__global__ void prep_kernel(const float* __restrict__ w1, const float* __restrict__ b1,
                            const float* __restrict__ w2, const float* __restrict__ b2,
                            const float* __restrict__ s_in, const float* __restrict__ s_w1,
                            const float* __restrict__ s_o1, const float* __restrict__ s_w2,
                            const float* __restrict__ s_o2) {
    const int t = threadIdx.x;
    const float si = s_in[0], sw1 = s_w1[0], so1 = s_o1[0], sw2 = s_w2[0], so2 = s_o2[0];
    if (t == 0) {
        g_consts[0] = 1.0f / si;
        g_consts[1] = (si * sw1) / so1;
        g_consts[2] = (so1 * sw2) / so2;
        g_consts[3] = so2;
    }
    if (t < 10) {
        g_b1i[t] = clampq(b1[t] / (si * sw1));
        g_b2i[t] = clampq(b2[t] / (so1 * sw2));
    }
    if (t < 90) {
        const int oc = t / 9, tap = t % 9;
        const int ky = tap / 3, kx = tap % 3;
        unsigned a = 0;
        #pragma unroll
        for (int c = 0; c < 4; c++) {
            int q = clampq(w1[((oc * 5 + c) * 3 + ky) * 3 + kx] / sw1);
            a |= ((unsigned)(q & 0xFF)) << (8 * c);
        }
        g_w1a[t] = a;
        uint2 p; p.x = 0u; p.y = 0u;
        #pragma unroll
        for (int c = 0; c < 8; c++) {
            int q = clampq(w2[((oc * 10 + c) * 3 + ky) * 3 + kx] / sw2);
            unsigned b = (unsigned)(q & 0xFF);
            if (c < 4) p.x |= b << (8 * c); else p.y |= b << (8 * (c - 4));
        }
        g_w2a[t] = p;
    }
    if (t < 30) {
        const int oc = t / 3, ky = t % 3;
        unsigned b = 0;
        #pragma unroll
        for (int kx = 0; kx < 3; kx++) {
            int q = clampq(w1[((oc * 5 + 4) * 3 + ky) * 3 + kx] / sw1);
            b |= ((unsigned)(q & 0xFF)) << (8 * kx);
        }
        g_w1b[t] = b;
        uint2 p; p.x = 0u; p.y = 0u;
        #pragma unroll
        for (int kx = 0; kx < 3; kx++) {
            int q8 = clampq(w2[((oc * 10 + 8) * 3 + ky) * 3 + kx] / sw2);
            int q9 = clampq(w2[((oc * 10 + 9) * 3 + ky) * 3 + kx] / sw2);
            p.x |= ((unsigned)(q8 & 0xFF)) << (8 * kx);
            p.y |= ((unsigned)(q9 & 0xFF)) << (8 * kx);
        }
        g_w2b[t] = p;
    }
}

__global__ __launch_bounds__(128)
void fused_conv_kernel(const float* __restrict__ x, float* __restrict__ out) {
    __shared__ unsigned xs4[20][38];        // x ch0-3 packed; cols 36,37 = 0 pad
    __shared__ unsigned xs1w[20][10];       // x ch4 byte plane (40B rows, word9=0)
    __shared__ uint2    ys2[18][36];        // y ch0-7 packed
    __shared__ unsigned char ys8b[18][40];  // y ch8 byte plane
    __shared__ unsigned char ys9b[18][40];  // y ch9 byte plane
    __shared__ unsigned w1a[90], w1b[30];
    __shared__ uint2    w2a[90], w2b[30];
    __shared__ int b1s[10], b2s[10];
    __shared__ float cs[4];

    const int tid = threadIdx.x;
    const int n  = blockIdx.z;
    const int ty = blockIdx.y * 16;
    const int tx = blockIdx.x * 32;

    if (tid < 90) { w1a[tid] = g_w1a[tid]; w2a[tid] = g_w2a[tid]; }
    if (tid < 30) { w1b[tid] = g_w1b[tid]; w2b[tid] = g_w2b[tid]; }
    if (tid < 10) { b1s[tid] = g_b1i[tid]; b2s[tid] = g_b2i[tid]; }
    if (tid < 4)  { cs[tid]  = g_consts[tid]; }
    if (tid < 20) { xs1w[tid][9] = 0u; }
    if (tid >= 20 && tid < 60) { int k = tid - 20; xs4[k >> 1][36 + (k & 1)] = 0u; }
    __syncthreads();
    const float inv_s_in = cs[0], m1 = cs[1], m2 = cs[2], so2 = cs[3];

    // ---- Phase A: load + quantize x tile (20 rows x 36 cols, 5 ch) ----
    const float* xb = x + (size_t)n * 1310720u;
    #pragma unroll
    for (int it = 0; it < 3; it++) {
        const int s = tid + it * 128;
        if (s < 360) {
            const int r = s / 18, p = s % 18, c = p * 2;
            const int gy = ty + r, gx = tx + c;
            float2 v0, v1, v2, v3, v4;
            if (gy < 512 && gx < 512) {
                const float* px = xb + (size_t)gy * 512 + gx;
                v0 = *(const float2*)px;
                v1 = *(const float2*)(px + 262144);
                v2 = *(const float2*)(px + 524288);
                v3 = *(const float2*)(px + 786432);
                v4 = *(const float2*)(px + 1048576);
            } else {
                v0 = v1 = v2 = v3 = v4 = make_float2(0.f, 0.f);
            }
            const unsigned a0 = q8b(v0.x * inv_s_in), e0 = q8b(v0.y * inv_s_in);
            const unsigned a1 = q8b(v1.x * inv_s_in), e1 = q8b(v1.y * inv_s_in);
            const unsigned a2 = q8b(v2.x * inv_s_in), e2 = q8b(v2.y * inv_s_in);
            const unsigned a3 = q8b(v3.x * inv_s_in), e3 = q8b(v3.y * inv_s_in);
            const unsigned a4 = q8b(v4.x * inv_s_in), e4 = q8b(v4.y * inv_s_in);
            xs4[r][c]     = __byte_perm(__byte_perm(a0, a1, 0x0040),
                                        __byte_perm(a2, a3, 0x0040), 0x5410);
            xs4[r][c + 1] = __byte_perm(__byte_perm(e0, e1, 0x0040),
                                        __byte_perm(e2, e3, 0x0040), 0x5410);
            ((unsigned short*)&xs1w[r][0])[p] =
                (unsigned short)(__byte_perm(a4, e4, 0x0040) & 0xFFFFu);
        }
    }
    __syncthreads();

    // ---- Phase B: conv1 (5->10), 6-px strips, 108 tasks, single pass ----
    if (tid < 108) {
        const int r = tid / 6, wi = tid % 6, cb = wi * 6;
        unsigned xv[3][8];
        #pragma unroll
        for (int ky = 0; ky < 3; ky++) {
            const uint2* rp = (const uint2*)&xs4[r + ky][cb];
            #pragma unroll
            for (int j = 0; j < 4; j++) {
                const uint2 t = rp[j];
                xv[ky][2 * j] = t.x; xv[ky][2 * j + 1] = t.y;
            }
        }
        unsigned win[3][6];
        const int wbase = cb >> 2;
        #pragma unroll
        for (int ky = 0; ky < 3; ky++) {
            const unsigned A = xs1w[r + ky][wbase];
            const unsigned B = xs1w[r + ky][wbase + 1];
            const unsigned C = xs1w[r + ky][wbase + 2];
            if ((cb & 3) == 0) {
                win[ky][0] = A;
                win[ky][1] = __funnelshift_r(A, B, 8);
                win[ky][2] = __funnelshift_r(A, B, 16);
                win[ky][3] = __funnelshift_r(A, B, 24);
                win[ky][4] = B;
                win[ky][5] = __funnelshift_r(B, C, 8);
            } else {
                win[ky][0] = __funnelshift_r(A, B, 16);
                win[ky][1] = __funnelshift_r(A, B, 24);
                win[ky][2] = B;
                win[ky][3] = __funnelshift_r(B, C, 8);
                win[ky][4] = __funnelshift_r(B, C, 16);
                win[ky][5] = __funnelshift_r(B, C, 24);
            }
        }
        unsigned o0[6], o1[6];
        #pragma unroll
        for (int oc = 0; oc < 10; oc++) {
            int acc[6];
            const int bb = b1s[oc];
            #pragma unroll
            for (int i = 0; i < 6; i++) acc[i] = bb;
            #pragma unroll
            for (int ky = 0; ky < 3; ky++) {
                #pragma unroll
                for (int kx = 0; kx < 3; kx++) {
                    const int w = (int)w1a[oc * 9 + ky * 3 + kx];
                    #pragma unroll
                    for (int i = 0; i < 6; i++)
                        acc[i] = __dp4a((int)xv[ky][i + kx], w, acc[i]);
                }
                const int wb = (int)w1b[oc * 3 + ky];
                #pragma unroll
                for (int i = 0; i < 6; i++)
                    acc[i] = __dp4a((int)win[ky][i], wb, acc[i]);
            }
            #pragma unroll
            for (int i = 0; i < 6; i++) {
                const unsigned q = q8b((float)acc[i] * m1);
                if (oc == 0)      o0[i] = q;
                else if (oc == 1) o0[i] = __byte_perm(o0[i], q, 0x3240);
                else if (oc == 2) o0[i] = __byte_perm(o0[i], q, 0x3410);
                else if (oc == 3) o0[i] = __byte_perm(o0[i], q, 0x4210);
                else if (oc == 4) o1[i] = q;
                else if (oc == 5) o1[i] = __byte_perm(o1[i], q, 0x3240);
                else if (oc == 6) o1[i] = __byte_perm(o1[i], q, 0x3410);
                else if (oc == 7) o1[i] = __byte_perm(o1[i], q, 0x4210);
                else if (oc == 8) ys8b[r][cb + i] = (unsigned char)q;
                else              ys9b[r][cb + i] = (unsigned char)q;
            }
        }
        #pragma unroll
        for (int i = 0; i < 6; i++)
            ys2[r][cb + i] = make_uint2(o0[i], o1[i]);
    }
    __syncthreads();

    // ---- Phase C: conv2 (10->10), 4-px strips, 128 tasks exact ----
    {
        const int r  = tid >> 3;
        const int wi = tid & 7;
        const int cb = wi * 4;
        uint4 yv[3][3];
        #pragma unroll
        for (int ky = 0; ky < 3; ky++) {
            const uint4* rp = (const uint4*)&ys2[r + ky][cb];
            yv[ky][0] = rp[0]; yv[ky][1] = rp[1]; yv[ky][2] = rp[2];
        }
        int w8[3][4], w9[3][4];
        #pragma unroll
        for (int ky = 0; ky < 3; ky++) {
            const unsigned* p8 = (const unsigned*)&ys8b[r + ky][0];
            const unsigned* p9 = (const unsigned*)&ys9b[r + ky][0];
            const unsigned A8 = p8[wi], B8 = p8[wi + 1];
            const unsigned A9 = p9[wi], B9 = p9[wi + 1];
            w8[ky][0] = (int)A8;
            w8[ky][1] = (int)__funnelshift_r(A8, B8, 8);
            w8[ky][2] = (int)__funnelshift_r(A8, B8, 16);
            w8[ky][3] = (int)__funnelshift_r(A8, B8, 24);
            w9[ky][0] = (int)A9;
            w9[ky][1] = (int)__funnelshift_r(A9, B9, 8);
            w9[ky][2] = (int)__funnelshift_r(A9, B9, 16);
            w9[ky][3] = (int)__funnelshift_r(A9, B9, 24);
        }
        const int gy = ty + r, gx = tx + cb;
        const bool valid = (gy < 508) && (gx < 508);
        float* ob = out + (size_t)n * 2580640u + (size_t)gy * 508u + gx;
        #pragma unroll
        for (int oc = 0; oc < 10; oc++) {
            int acc[4];
            const int bb = b2s[oc];
            #pragma unroll
            for (int i = 0; i < 4; i++) acc[i] = bb;
            #pragma unroll
            for (int ky = 0; ky < 3; ky++) {
                #pragma unroll
                for (int kx = 0; kx < 3; kx++) {
                    const uint2 w = w2a[oc * 9 + ky * 3 + kx];
                    #pragma unroll
                    for (int i = 0; i < 4; i++) {
                        const int j = i + kx;
                        const unsigned lo = (j & 1) ? yv[ky][j >> 1].z : yv[ky][j >> 1].x;
                        const unsigned hi = (j & 1) ? yv[ky][j >> 1].w : yv[ky][j >> 1].y;
                        acc[i] = __dp4a((int)lo, (int)w.x, acc[i]);
                        acc[i] = __dp4a((int)hi, (int)w.y, acc[i]);
                    }
                }
                const uint2 wb = w2b[oc * 3 + ky];
                #pragma unroll
                for (int i = 0; i < 4; i++) {
                    acc[i] = __dp4a(w8[ky][i], (int)wb.x, acc[i]);
                    acc[i] = __dp4a(w9[ky][i], (int)wb.y, acc[i]);
                }
            }
            if (valid) {
                float4 v;
                v.x = (float)qclampf((float)acc[0] * m2) * so2;
                v.y = (float)qclampf((float)acc[1] * m2) * so2;
                v.z = (float)qclampf((float)acc[2] * m2) * so2;
                v.w = (float)qclampf((float)acc[3] * m2) * so2;
                *(float4*)(ob + (size_t)oc * 258064u) = v;
            }
        }
    }
}

extern "C" void kernel_launch(void* const* d_in, const int* in_sizes, int n_in,
                              void* d_out, int out_size) {
    const float* x    = (const float*)d_in[0];
    const float* w1   = (const float*)d_in[1];
    const float* b1   = (const float*)d_in[2];
    const float* w2   = (const float*)d_in[3];
    const float* b2   = (const float*)d_in[4];
    const float* s_in = (const float*)d_in[5];
    const float* s_w1 = (const float*)d_in[6];
    const float* s_o1 = (const float*)d_in[7];
    const float* s_w2 = (const float*)d_in[8];
    const float* s_o2 = (const float*)d_in[9];

    prep_kernel<<<1, 128>>>(w1, b1, w2, b2, s_in, s_w1, s_o1, s_w2, s_o2);

    dim3 grid(16, 32, 32);   // 32-wide x 16-tall tiles over 508x508, batch 32
    fused_conv_kernel<<<grid, 128>>>(x, (float*)d_out);
}

// round 5
// speedup vs baseline: 1.7956x; 1.0108x over previous
#include <cuda_runtime.h>
#include <cstdint>

// ============================================================================
// Fused int8 fake-quant conv3x3(5->10) + conv3x3(10->10), pow2 scales.
// Bit-exact integer arithmetic. R5 = R4 with the STS.128 alignment fix:
// xs4 rows padded to 40 words (160B, 16B-aligned) so uint4 stores are legal.
// 32x32 tiles / 256 threads, launch_bounds(256,3), float4 phase-A loads.
// ============================================================================

__device__ float g_consts[4];       // inv_s_in, m1, m2, s_o2
__device__ int   g_b1i[10];
__device__ int   g_b2i[10];
__device__ unsigned g_w1a[90];      // [oc*9+tap]: ch0-3 packed
__device__ unsigned g_w1b[30];      // [oc*3+ky]:  [w4_kx0,w4_kx1,w4_kx2,0]
__device__ uint2    g_w2a[90];      // [oc*9+tap]: ch0-7 packed
__device__ uint2    g_w2b[30];      // [oc*3+ky]:  .x=ch8 row word, .y=ch9

__device__ __forceinline__ int clampq(float v) {
    int q = __float2int_rn(v);
    return max(-128, min(127, q));
}
// round-half-even + saturate to s8 (low byte usable)
__device__ __forceinline__ unsigned q8b(float v) {
    unsigned r;
    asm("cvt.rni.sat.s8.f32 %0, %1;" : "=r"(r) : "f"(v));
    return r;
}
// full-integer result: float clamp then round
__device__ __forceinline__ int qclampf(float v) {
    return __float2int_rn(fminf(fmaxf(v, -128.0f), 127.0f));
}

__global__ void prep_kernel(const float* __restrict__ w1, const float* __restrict__ b1,
                            const float* __restrict__ w2, const float* __restrict__ b2,
                            const float* __restrict__ s_in, const float* __restrict__ s_w1,
                            const float* __restrict__ s_o1, const float* __restrict__ s_w2,
                            const float* __restrict__ s_o2) {
    const int t = threadIdx.x;
    const float si = s_in[0], sw1 = s_w1[0], so1 = s_o1[0], sw2 = s_w2[0], so2 = s_o2[0];
    if (t == 0) {
        g_consts[0] = 1.0f / si;
        g_consts[1] = (si * sw1) / so1;
        g_consts[2] = (so1 * sw2) / so2;
        g_consts[3] = so2;
    }
    if (t < 10) {
        g_b1i[t] = clampq(b1[t] / (si * sw1));
        g_b2i[t] = clampq(b2[t] / (so1 * sw2));
    }
    if (t < 90) {
        const int oc = t / 9, tap = t % 9;
        const int ky = tap / 3, kx = tap % 3;
        unsigned a = 0;
        #pragma unroll
        for (int c = 0; c < 4; c++) {
            int q = clampq(w1[((oc * 5 + c) * 3 + ky) * 3 + kx] / sw1);
            a |= ((unsigned)(q & 0xFF)) << (8 * c);
        }
        g_w1a[t] = a;
        uint2 p; p.x = 0u; p.y = 0u;
        #pragma unroll
        for (int c = 0; c < 8; c++) {
            int q = clampq(w2[((oc * 10 + c) * 3 + ky) * 3 + kx] / sw2);
            unsigned b = (unsigned)(q & 0xFF);
            if (c < 4) p.x |= b << (8 * c); else p.y |= b << (8 * (c - 4));
        }
        g_w2a[t] = p;
    }
    if (t < 30) {
        const int oc = t / 3, ky = t % 3;
        unsigned b = 0;
        #pragma unroll
        for (int kx = 0; kx < 3; kx++) {
            int q = clampq(w1[((oc * 5 + 4) * 3 + ky) * 3 + kx] / sw1);
            b |= ((unsigned)(q & 0xFF)) << (8 * kx);
        }
        g_w1b[t] = b;
        uint2 p; p.x = 0u; p.y = 0u;
        #pragma unroll
        for (int kx = 0; kx < 3; kx++) {
            int q8 = clampq(w2[((oc * 10 + 8) * 3 + ky) * 3 + kx] / sw2);
            int q9 = clampq(w2[((oc * 10 + 9) * 3 + ky) * 3 + kx] / sw2);
            p.x |= ((unsigned)(q8 & 0xFF)) << (8 * kx);
            p.y |= ((unsigned)(q9 & 0xFF)) << (8 * kx);
        }
        g_w2b[t] = p;
    }
}

__global__ __launch_bounds__(256, 3)
void fused_conv_kernel(const float* __restrict__ x, float* __restrict__ out) {
    __shared__ unsigned xs4[36][40];        // x ch0-3 packed; 160B rows (16B align)
    __shared__ unsigned xs1w[36][10];       // x ch4 byte plane (word 9 = 0)
    __shared__ uint2    ys2[34][36];        // y ch0-7 packed (288B rows)
    __shared__ unsigned char ys8b[34][40];  // y ch8 byte plane
    __shared__ unsigned char ys9b[34][40];  // y ch9 byte plane
    __shared__ unsigned w1a[90], w1b[30];
    __shared__ uint2    w2a[90], w2b[30];
    __shared__ int b1s[10], b2s[10];
    __shared__ float cs[4];

    const int tid = threadIdx.x;
    const int n  = blockIdx.z;
    const int ty = blockIdx.y * 32;
    const int tx = blockIdx.x * 32;

    if (tid < 90) { w1a[tid] = g_w1a[tid]; w2a[tid] = g_w2a[tid]; }
    if (tid < 30) { w1b[tid] = g_w1b[tid]; w2b[tid] = g_w2b[tid]; }
    if (tid < 10) { b1s[tid] = g_b1i[tid]; b2s[tid] = g_b2i[tid]; }
    if (tid < 4)  { cs[tid]  = g_consts[tid]; }
    if (tid >= 96  && tid < 132) { xs1w[tid - 96][9] = 0u; }
    if (tid >= 160 && tid < 232) { int k = tid - 160; xs4[k >> 1][36 + (k & 1)] = 0u; }
    __syncthreads();
    const float inv_s_in = cs[0], m1 = cs[1], m2 = cs[2], so2 = cs[3];

    // ---- Phase A: load + quantize x tile (36 rows x 36 cols, 5 ch) ----
    // 324 tasks: each = 4 consecutive pixels, 5 channels, float4 loads.
    const float* xb = x + (size_t)n * 1310720u;
    #pragma unroll
    for (int it = 0; it < 2; it++) {
        const int s = tid + it * 256;
        if (s < 324) {
            const int r = s / 9, c4 = s % 9, c = c4 * 4;
            const int gy = ty + r, gx = tx + c;
            float4 v0, v1, v2, v3, v4;
            if (gy < 512 && gx < 512) {
                const float* px = xb + (size_t)gy * 512 + gx;
                v0 = *(const float4*)px;
                v1 = *(const float4*)(px + 262144);
                v2 = *(const float4*)(px + 524288);
                v3 = *(const float4*)(px + 786432);
                v4 = *(const float4*)(px + 1048576);
            } else {
                v0 = v1 = v2 = v3 = v4 = make_float4(0.f, 0.f, 0.f, 0.f);
            }
            uint4 w;
            w.x = __byte_perm(__byte_perm(q8b(v0.x * inv_s_in), q8b(v1.x * inv_s_in), 0x0040),
                              __byte_perm(q8b(v2.x * inv_s_in), q8b(v3.x * inv_s_in), 0x0040), 0x5410);
            w.y = __byte_perm(__byte_perm(q8b(v0.y * inv_s_in), q8b(v1.y * inv_s_in), 0x0040),
                              __byte_perm(q8b(v2.y * inv_s_in), q8b(v3.y * inv_s_in), 0x0040), 0x5410);
            w.z = __byte_perm(__byte_perm(q8b(v0.z * inv_s_in), q8b(v1.z * inv_s_in), 0x0040),
                              __byte_perm(q8b(v2.z * inv_s_in), q8b(v3.z * inv_s_in), 0x0040), 0x5410);
            w.w = __byte_perm(__byte_perm(q8b(v0.w * inv_s_in), q8b(v1.w * inv_s_in), 0x0040),
                              __byte_perm(q8b(v2.w * inv_s_in), q8b(v3.w * inv_s_in), 0x0040), 0x5410);
            *(uint4*)&xs4[r][c] = w;   // 160B rows + c%4==0 -> 16B aligned
            xs1w[r][c4] = __byte_perm(__byte_perm(q8b(v4.x * inv_s_in), q8b(v4.y * inv_s_in), 0x0040),
                                      __byte_perm(q8b(v4.z * inv_s_in), q8b(v4.w * inv_s_in), 0x0040), 0x5410);
        }
    }
    __syncthreads();

    // ---- Phase B: conv1 (5->10), 6-px strips, 204 tasks, single pass ----
    if (tid < 204) {
        const int r = tid / 6, wi = tid % 6, cb = wi * 6;
        unsigned xv[3][8];
        #pragma unroll
        for (int ky = 0; ky < 3; ky++) {
            const uint2* rp = (const uint2*)&xs4[r + ky][cb];   // cb even -> 8B aligned
            #pragma unroll
            for (int j = 0; j < 4; j++) {
                const uint2 t = rp[j];
                xv[ky][2 * j] = t.x; xv[ky][2 * j + 1] = t.y;
            }
        }
        unsigned win[3][6];
        const int wbase = cb >> 2;
        #pragma unroll
        for (int ky = 0; ky < 3; ky++) {
            const unsigned A = xs1w[r + ky][wbase];
            const unsigned B = xs1w[r + ky][wbase + 1];
            const unsigned C = xs1w[r + ky][wbase + 2];
            if ((cb & 3) == 0) {
                win[ky][0] = A;
                win[ky][1] = __funnelshift_r(A, B, 8);
                win[ky][2] = __funnelshift_r(A, B, 16);
                win[ky][3] = __funnelshift_r(A, B, 24);
                win[ky][4] = B;
                win[ky][5] = __funnelshift_r(B, C, 8);
            } else {
                win[ky][0] = __funnelshift_r(A, B, 16);
                win[ky][1] = __funnelshift_r(A, B, 24);
                win[ky][2] = B;
                win[ky][3] = __funnelshift_r(B, C, 8);
                win[ky][4] = __funnelshift_r(B, C, 16);
                win[ky][5] = __funnelshift_r(B, C, 24);
            }
        }
        unsigned o0[6], o1[6];
        #pragma unroll
        for (int oc = 0; oc < 10; oc++) {
            int acc[6];
            const int bb = b1s[oc];
            #pragma unroll
            for (int i = 0; i < 6; i++) acc[i] = bb;
            #pragma unroll
            for (int ky = 0; ky < 3; ky++) {
                #pragma unroll
                for (int kx = 0; kx < 3; kx++) {
                    const int w = (int)w1a[oc * 9 + ky * 3 + kx];
                    #pragma unroll
                    for (int i = 0; i < 6; i++)
                        acc[i] = __dp4a((int)xv[ky][i + kx], w, acc[i]);
                }
                const int wb = (int)w1b[oc * 3 + ky];
                #pragma unroll
                for (int i = 0; i < 6; i++)
                    acc[i] = __dp4a((int)win[ky][i], wb, acc[i]);
            }
            #pragma unroll
            for (int i = 0; i < 6; i++) {
                const unsigned q = q8b((float)acc[i] * m1);
                if (oc == 0)      o0[i] = q;
                else if (oc == 1) o0[i] = __byte_perm(o0[i], q, 0x3240);
                else if (oc == 2) o0[i] = __byte_perm(o0[i], q, 0x3410);
                else if (oc == 3) o0[i] = __byte_perm(o0[i], q, 0x4210);
                else if (oc == 4) o1[i] = q;
                else if (oc == 5) o1[i] = __byte_perm(o1[i], q, 0x3240);
                else if (oc == 6) o1[i] = __byte_perm(o1[i], q, 0x3410);
                else if (oc == 7) o1[i] = __byte_perm(o1[i], q, 0x4210);
                else if (oc == 8) ys8b[r][cb + i] = (unsigned char)q;
                else              ys9b[r][cb + i] = (unsigned char)q;
            }
        }
        #pragma unroll
        for (int i = 0; i < 6; i++)
            ys2[r][cb + i] = make_uint2(o0[i], o1[i]);
    }
    __syncthreads();

    // ---- Phase C: conv2 (10->10), 4-px strips, 256 tasks exact ----
    {
        const int r  = tid >> 3;          // 0..31
        const int wi = tid & 7;           // 0..7
        const int cb = wi * 4;
        uint4 yv[3][3];
        #pragma unroll
        for (int ky = 0; ky < 3; ky++) {
            const uint4* rp = (const uint4*)&ys2[r + ky][cb];   // 288B rows, cb*8 mult of 32
            yv[ky][0] = rp[0]; yv[ky][1] = rp[1]; yv[ky][2] = rp[2];
        }
        int w8[3][4], w9[3][4];
        #pragma unroll
        for (int ky = 0; ky < 3; ky++) {
            const unsigned* p8 = (const unsigned*)&ys8b[r + ky][0];
            const unsigned* p9 = (const unsigned*)&ys9b[r + ky][0];
            const unsigned A8 = p8[wi], B8 = p8[wi + 1];
            const unsigned A9 = p9[wi], B9 = p9[wi + 1];
            w8[ky][0] = (int)A8;
            w8[ky][1] = (int)__funnelshift_r(A8, B8, 8);
            w8[ky][2] = (int)__funnelshift_r(A8, B8, 16);
            w8[ky][3] = (int)__funnelshift_r(A8, B8, 24);
            w9[ky][0] = (int)A9;
            w9[ky][1] = (int)__funnelshift_r(A9, B9, 8);
            w9[ky][2] = (int)__funnelshift_r(A9, B9, 16);
            w9[ky][3] = (int)__funnelshift_r(A9, B9, 24);
        }
        const int gy = ty + r, gx = tx + cb;
        const bool valid = (gy < 508) && (gx < 508);
        float* ob = out + (size_t)n * 2580640u + (size_t)gy * 508u + gx;
        #pragma unroll
        for (int oc = 0; oc < 10; oc++) {
            int acc[4];
            const int bb = b2s[oc];
            #pragma unroll
            for (int i = 0; i < 4; i++) acc[i] = bb;
            #pragma unroll
            for (int ky = 0; ky < 3; ky++) {
                #pragma unroll
                for (int kx = 0; kx < 3; kx++) {
                    const uint2 w = w2a[oc * 9 + ky * 3 + kx];
                    #pragma unroll
                    for (int i = 0; i < 4; i++) {
                        const int j = i + kx;
                        const unsigned lo = (j & 1) ? yv[ky][j >> 1].z : yv[ky][j >> 1].x;
                        const unsigned hi = (j & 1) ? yv[ky][j >> 1].w : yv[ky][j >> 1].y;
                        acc[i] = __dp4a((int)lo, (int)w.x, acc[i]);
                        acc[i] = __dp4a((int)hi, (int)w.y, acc[i]);
                    }
                }
                const uint2 wb = w2b[oc * 3 + ky];
                #pragma unroll
                for (int i = 0; i < 4; i++) {
                    acc[i] = __dp4a(w8[ky][i], (int)wb.x, acc[i]);
                    acc[i] = __dp4a(w9[ky][i], (int)wb.y, acc[i]);
                }
            }
            if (valid) {
                float4 v;
                v.x = (float)qclampf((float)acc[0] * m2) * so2;
                v.y = (float)qclampf((float)acc[1] * m2) * so2;
                v.z = (float)qclampf((float)acc[2] * m2) * so2;
                v.w = (float)qclampf((float)acc[3] * m2) * so2;
                *(float4*)(ob + (size_t)oc * 258064u) = v;
            }
        }
    }
}

extern "C" void kernel_launch(void* const* d_in, const int* in_sizes, int n_in,
                              void* d_out, int out_size) {
    const float* x    = (const float*)d_in[0];
    const float* w1   = (const float*)d_in[1];
    const float* b1   = (const float*)d_in[2];
    const float* w2   = (const float*)d_in[3];
    const float* b2   = (const float*)d_in[4];
    const float* s_in = (const float*)d_in[5];
    const float* s_w1 = (const float*)d_in[6];
    const float* s_o1 = (const float*)d_in[7];
    const float* s_w2 = (const float*)d_in[8];
    const float* s_o2 = (const float*)d_in[9];

    prep_kernel<<<1, 128>>>(w1, b1, w2, b2, s_in, s_w1, s_o1, s_w2, s_o2);

    dim3 grid(16, 16, 32);   // 32x32 tiles over 508x508, batch 32
    fused_conv_kernel<<<grid, 256>>>(x, (float*)d_out);
}